// round 16
// baseline (speedup 1.0000x reference)
#include <cuda_runtime.h>
#include <cuda_fp16.h>
#include <mma.h>
#include <cstdint>

using namespace nvcuda;

// Problem constants
#define B_WIN   4096
#define NTOK    49
#define CDIM    384
#define NHEADS  12
#define HDIM    32
#define NWIN    1024
#define SCALE_Q 0.17677669529663687f  // 32^-0.5

// Precomputed-weight globals (~1.2 MB)
__device__ __align__(256) __half g_wqkv[NHEADS * 96 * CDIM];  // head-permuted qkv_w
__device__ __align__(256) __half g_wpj[CDIM * CDIM];          // proj_w fp16

// Shared memory layout (byte offsets) — identical to R15 (2,453 µs)
#define SM_XH   0        // Xh: 64 x 392 half = 50176
#define SM_SF   50176    // GEMM staging 64x196 f32 | S 2x64x68 f32 + Sh 2x64x72 half
#define SM_WB   103424   // W staging 2 x 13824 halves = 55296 B; qkv aliases
#define SM_OH   158720   // Oh: 64 x 392 half = 50176
#define SM_MS   208896   // mask f32: 49 x 50 = 9800 (+pad)
#define SM_RB   218696   // rpb all heads fp16: 12 x 169 = 4056 (+pad)
#define SM_PAR  222752   // qkv_b(1152)+proj_b(384)+lamb(12) f32 = 6192
#define SMEM_BYTES 228944

#define XLD   392        // Xh/Oh ld (halves)
#define WLD   72         // qkv W staging ld (halves)
#define WBUF  13824      // halves per W buffer
#define KVLD  40         // qkv ld (halves)
#define QLD   196        // GEMM staging ld (floats)
#define SLD   68         // S f32 ld
#define SHLD  72         // Sh ld (halves)
#define PQLD  100        // proj staging ld (floats)
#define SH_OFF 34816     // byte offset of Sh inside SF region
#define WLD2  136        // proj W staging ld (halves), Kc=128 (+8 pad)
#define NT    384

// ---------------------------------------------------------------------------
// Fused weight precompute: one kernel (so ncu -s 5 lands on the main kernel)
// ---------------------------------------------------------------------------
#define NQKV (NHEADS * 96 * CDIM)     // 442368
#define NPJ  (CDIM * CDIM)            // 147456
__global__ void prep_weights(const float* __restrict__ qkv_w,
                             const float* __restrict__ proj_w)
{
    int idx = blockIdx.x * 256 + threadIdx.x;
    if (idx < NQKV) {
        int h   = idx / (96 * CDIM);
        int rem = idx % (96 * CDIM);
        int j   = rem / CDIM;
        int k   = rem % CDIM;
        int g   = (j >> 5) * CDIM + h * HDIM + (j & 31);
        g_wqkv[idx] = __float2half_rn(qkv_w[(size_t)g * CDIM + k]);
    } else if (idx < NQKV + NPJ) {
        int i2 = idx - NQKV;
        g_wpj[i2] = __float2half_rn(proj_w[i2]);
    }
}

// ---------------------------------------------------------------------------
// Fused window attention: one block per window, 384 threads, head-pair groups,
// register-staged double-buffered GEMM; proj single-fp16, Kc=128; warp-local
// O->Oh conversion.
// ---------------------------------------------------------------------------
__global__ void __launch_bounds__(NT, 1)
winattn_kernel(const float* __restrict__ x,
               const float* __restrict__ mask,
               const float* __restrict__ qkv_b,
               const float* __restrict__ proj_b,
               const float* __restrict__ rpb,
               const float* __restrict__ lamb,
               float* __restrict__ out)
{
    extern __shared__ __align__(16) char smraw[];
    __half* Xh  = (__half*)(smraw + SM_XH);
    float*  Sf  = (float*)(smraw + SM_SF);
    __half* Sh  = (__half*)(smraw + SM_SF + SH_OFF);
    __half* WB  = (__half*)(smraw + SM_WB);
    __half* qkv = WB;                               // aliases WB (phase-disjoint)
    __half* Oh  = (__half*)(smraw + SM_OH);
    float*  ms  = (float*)(smraw + SM_MS);
    __half* rb  = (__half*)(smraw + SM_RB);
    float*  par = (float*)(smraw + SM_PAR);

    const int tid = threadIdx.x;
    const int wp  = tid >> 5;
    const int l   = tid & 31;
    const int w   = blockIdx.x;

    // qkv GEMM staging map: 192x64-half chunk = 1536 int4, 4 per thread
    int sj[4], sk[4];
#pragma unroll
    for (int i = 0; i < 4; ++i) {
        int v = tid + i * NT;
        sj[i] = v >> 3;
        sk[i] = (v & 7) << 3;
    }
    // proj staging map: 96x128-half chunk = 1536 int4, 4 per thread
    int pj[4], pk[4];
#pragma unroll
    for (int i = 0; i < 4; ++i) {
        int v = tid + i * NT;
        pj[i] = v >> 4;
        pk[i] = (v & 15) << 3;
    }

    // ---- init ----
    for (int t = tid; t < 49 * 96; t += NT) {
        int r = t / 96, c4 = (t % 96) * 4;
        float4 v = *(const float4*)&x[((size_t)w * NTOK + r) * CDIM + c4];
        *(__half2*)&Xh[r * XLD + c4]     = __floats2half2_rn(v.x, v.y);
        *(__half2*)&Xh[r * XLD + c4 + 2] = __floats2half2_rn(v.z, v.w);
    }
    for (int t = tid; t < 15 * 196; t += NT) {        // zero pad rows 49..63
        int r = 49 + t / 196, c2 = (t % 196) * 2;
        __half2 z = __floats2half2_rn(0.0f, 0.0f);
        *(__half2*)&Xh[r * XLD + c2] = z;
        *(__half2*)&Oh[r * XLD + c2] = z;
    }
    {
        const float* mrow = mask + (size_t)(w & (NWIN - 1)) * (NTOK * NTOK);
        for (int t = tid; t < NTOK * NTOK; t += NT)
            ms[(t / 49) * 50 + (t % 49)] = mrow[t];
    }
    for (int t = tid; t < NHEADS * 169; t += NT)
        rb[t] = __float2half_rn(rpb[(t % 169) * NHEADS + (t / 169)]);
    for (int t = tid; t < 1548; t += NT)
        par[t] = (t < 1152) ? qkv_b[t] : (t < 1536 ? proj_b[t - 1152] : lamb[t - 1536]);
    __syncthreads();

    const int mrow0 = (wp & 1) * 32;     // GEMM m-base (2 x 16-row frags)
    const int ngq   = (wp >> 1) * 32;    // QKV GEMM n-base (6 groups of 32)

    // softmax lane constants
    const int j0 = l, j1 = l + 32;
    const int j0d = j0 / 7, j0m = j0 % 7;
    const int j1d = j1 / 7, j1m = j1 % 7;

    // =============== 6 groups of 2 heads ===============
    for (int g = 0; g < 6; ++g) {
        const int h0 = 2 * g;
        const __half* Wg = g_wqkv + (size_t)h0 * (96 * CDIM);

        // ---- QKV GEMM: 64x192 = Xh @ Wg^T, Kc=64, register-staged dbl buffer ----
        wmma::fragment<wmma::accumulator, 16, 16, 16, float> acc[2][2];
#pragma unroll
        for (int i = 0; i < 2; ++i)
#pragma unroll
            for (int j = 0; j < 2; ++j) wmma::fill_fragment(acc[i][j], 0.0f);

        int4 st[4];
#pragma unroll
        for (int i = 0; i < 4; ++i)
            st[i] = *(const int4*)(Wg + (size_t)sj[i] * CDIM + sk[i]);
#pragma unroll
        for (int i = 0; i < 4; ++i)
            *(int4*)(WB + sj[i] * WLD + sk[i]) = st[i];
        __syncthreads();

        for (int c = 0; c < 6; ++c) {
            if (c < 5) {
#pragma unroll
                for (int i = 0; i < 4; ++i)
                    st[i] = *(const int4*)(Wg + (size_t)sj[i] * CDIM + (c + 1) * 64 + sk[i]);
            }
            const __half* Wc = WB + (c & 1) * WBUF;
#pragma unroll
            for (int ks = 0; ks < 4; ++ks) {
                wmma::fragment<wmma::matrix_a, 16, 16, 16, __half, wmma::row_major> a0, a1;
                wmma::load_matrix_sync(a0, &Xh[mrow0 * XLD + c * 64 + ks * 16], XLD);
                wmma::load_matrix_sync(a1, &Xh[(mrow0 + 16) * XLD + c * 64 + ks * 16], XLD);
                wmma::fragment<wmma::matrix_b, 16, 16, 16, __half, wmma::col_major> b0, b1;
                wmma::load_matrix_sync(b0, &Wc[ngq * WLD + ks * 16], WLD);
                wmma::load_matrix_sync(b1, &Wc[(ngq + 16) * WLD + ks * 16], WLD);
                wmma::mma_sync(acc[0][0], a0, b0, acc[0][0]);
                wmma::mma_sync(acc[0][1], a0, b1, acc[0][1]);
                wmma::mma_sync(acc[1][0], a1, b0, acc[1][0]);
                wmma::mma_sync(acc[1][1], a1, b1, acc[1][1]);
            }
            if (c < 5) {
#pragma unroll
                for (int i = 0; i < 4; ++i)
                    *(int4*)(WB + ((c + 1) & 1) * WBUF + sj[i] * WLD + sk[i]) = st[i];
            }
            __syncthreads();
        }
#pragma unroll
        for (int i = 0; i < 2; ++i)
#pragma unroll
            for (int j = 0; j < 2; ++j)
                wmma::store_matrix_sync(&Sf[(mrow0 + i * 16) * QLD + ngq + j * 16],
                                        acc[i][j], QLD, wmma::mem_row_major);
        __syncthreads();

        // ---- bias + q-scale + convert -> qkv fp16 ----
        for (int t = tid; t < 49 * 192; t += NT) {
            int r = t / 192, cc = t % 192;
            int hh = cc / 96, c2 = cc % 96, which = c2 >> 5, d = c2 & 31;
            float vv = Sf[r * QLD + cc] + par[which * CDIM + (h0 + hh) * HDIM + d];
            if (which == 0) vv *= SCALE_Q;
            qkv[hh * 7680 + which * 2560 + r * KVLD + d] = __float2half_rn(vv);
        }
        __syncthreads();

        // ---- S = q @ k^T : 32 tiles over 12 warps; Sh pad rows zeroed here ----
        for (int t = wp; t < 32; t += 12) {
            int hh = t >> 4, mi = (t >> 2) & 3, nj = t & 3;
            const __half* qh = qkv + hh * 7680;
            const __half* kh = qh + 2560;
            wmma::fragment<wmma::accumulator, 16, 16, 16, float> sacc;
            wmma::fill_fragment(sacc, 0.0f);
#pragma unroll
            for (int ks = 0; ks < 2; ++ks) {
                wmma::fragment<wmma::matrix_a, 16, 16, 16, __half, wmma::row_major> a1;
                wmma::fragment<wmma::matrix_b, 16, 16, 16, __half, wmma::col_major> b1;
                wmma::load_matrix_sync(a1, &qh[mi * 16 * KVLD + ks * 16], KVLD);
                wmma::load_matrix_sync(b1, &kh[nj * 16 * KVLD + ks * 16], KVLD);
                wmma::mma_sync(sacc, a1, b1, sacc);
            }
            wmma::store_matrix_sync(&Sf[hh * 4352 + mi * 16 * SLD + nj * 16],
                                    sacc, SLD, wmma::mem_row_major);
        }
        // zero Sh pad rows 49..63 (both heads), cols 0..63 — 960 half2
        for (int t = tid; t < 960; t += NT) {
            int hh = t / 480, rem = t - hh * 480;
            int r = 49 + rem / 32, c2 = (rem % 32) * 2;
            *(__half2*)&Sh[hh * 4608 + r * SHLD + c2] = __floats2half2_rn(0.0f, 0.0f);
        }
        __syncthreads();

        // ---- softmax (+rpb+mask, lamb rescale) -> Sh fp16, 98 valid rows ----
        for (int t = wp; t < 98; t += 12) {
            const int hh = (t >= 49) ? 1 : 0;
            const int i  = t - hh * 49;
            __half* ShH = Sh + hh * 4608;
            const float lam1 = 1.0f + par[1536 + h0 + hh];
            const float invn = 1.0f / (float)NTOK;
            const __half* rbh = rb + (h0 + hh) * 169;
            const int i7 = i / 7, im = i - i7 * 7;
            const int r0 = (i7 - j0d + 6) * 13 + (im - j0m + 6);
            float s0 = Sf[hh * 4352 + i * SLD + j0] + __half2float(rbh[r0]) + ms[i * 50 + j0];
            float s1 = -1e30f;
            if (j1 < NTOK) {
                const int r1 = (i7 - j1d + 6) * 13 + (im - j1m + 6);
                s1 = Sf[hh * 4352 + i * SLD + j1] + __half2float(rbh[r1]) + ms[i * 50 + j1];
            }
            float mx = fmaxf(s0, s1);
#pragma unroll
            for (int off = 16; off > 0; off >>= 1)
                mx = fmaxf(mx, __shfl_xor_sync(0xffffffffu, mx, off));
            float e0 = __expf(s0 - mx);
            float e1 = (j1 < NTOK) ? __expf(s1 - mx) : 0.0f;
            float sm = e0 + e1;
#pragma unroll
            for (int off = 16; off > 0; off >>= 1)
                sm += __shfl_xor_sync(0xffffffffu, sm, off);
            const float inv = 1.0f / sm;
            ShH[i * SHLD + j0] = __float2half_rn(invn + (e0 * inv - invn) * lam1);
            ShH[i * SHLD + j1] = (j1 < NTOK)
                ? __float2half_rn(invn + (e1 * inv - invn) * lam1)
                : __float2half_rn(0.0f);
        }
        __syncthreads();

        // ---- O = attn @ v : 16 tiles over 12 warps, warp-local convert ----
        for (int t = wp; t < 16; t += 12) {
            int hh = t >> 3, mi = (t >> 1) & 3, nj = t & 1;
            const __half* ShH = Sh + hh * 4608;
            const __half* vhh = qkv + hh * 7680 + 5120;
            wmma::fragment<wmma::accumulator, 16, 16, 16, float> oacc;
            wmma::fill_fragment(oacc, 0.0f);
#pragma unroll
            for (int ks = 0; ks < 4; ++ks) {
                wmma::fragment<wmma::matrix_a, 16, 16, 16, __half, wmma::row_major> a1;
                wmma::fragment<wmma::matrix_b, 16, 16, 16, __half, wmma::row_major> b1;
                wmma::load_matrix_sync(a1, &ShH[mi * 16 * SHLD + ks * 16], SHLD);
                wmma::load_matrix_sync(b1, &vhh[ks * 16 * KVLD + nj * 16], KVLD);
                wmma::mma_sync(oacc, a1, b1, oacc);
            }
            float* dstF = &Sf[hh * 4352 + mi * 16 * SLD + nj * 16];
            wmma::store_matrix_sync(dstF, oacc, SLD, wmma::mem_row_major);
            __syncwarp();
            // convert own 16x16 tile -> Oh
#pragma unroll
            for (int k = 0; k < 8; ++k) {
                int e = l + k * 32;
                int r = e >> 4, cc = e & 15;
                int i = mi * 16 + r;
                if (i < NTOK)
                    Oh[i * XLD + (h0 + hh) * HDIM + nj * 16 + cc] =
                        __float2half_rn(dstF[r * SLD + cc]);
            }
            __syncwarp();
        }
        __syncthreads();   // Oh written; qkv (WB) free for next group staging
    }

    // =============== proj: out = Oh @ proj_w^T + b (single fp16, Kc=128) ===============
    const int np6 = (wp >> 1);      // n-tile 0..5 (16 cols each)

    int4 pst[4];
#pragma unroll
    for (int i = 0; i < 4; ++i)
        pst[i] = *(const int4*)(g_wpj + (size_t)pj[i] * CDIM + pk[i]);
#pragma unroll
    for (int i = 0; i < 4; ++i)
        *(int4*)(WB + pj[i] * WLD2 + pk[i]) = pst[i];
    __syncthreads();

    int cb = 0;   // global chunk parity: current chunk resides in buf (cb & 1)
    for (int p = 0; p < 4; ++p) {
        wmma::fragment<wmma::accumulator, 16, 16, 16, float> acc2[2];
        wmma::fill_fragment(acc2[0], 0.0f);
        wmma::fill_fragment(acc2[1], 0.0f);

        for (int c = 0; c < 3; ++c, ++cb) {
            const bool more = (c < 2) || (p < 3);
            if (more) {
                const int np_ = (c < 2) ? p : p + 1;
                const int nc_ = (c < 2) ? c + 1 : 0;
#pragma unroll
                for (int i = 0; i < 4; ++i)
                    pst[i] = *(const int4*)(g_wpj
                             + (size_t)(np_ * 96 + pj[i]) * CDIM + nc_ * 128 + pk[i]);
            }
            const __half* Wc = WB + (cb & 1) * WBUF;
#pragma unroll
            for (int ks = 0; ks < 8; ++ks) {
                wmma::fragment<wmma::matrix_a, 16, 16, 16, __half, wmma::row_major> a0, a1;
                wmma::load_matrix_sync(a0, &Oh[mrow0 * XLD + c * 128 + ks * 16], XLD);
                wmma::load_matrix_sync(a1, &Oh[(mrow0 + 16) * XLD + c * 128 + ks * 16], XLD);
                wmma::fragment<wmma::matrix_b, 16, 16, 16, __half, wmma::col_major> b1;
                wmma::load_matrix_sync(b1, &Wc[np6 * 16 * WLD2 + ks * 16], WLD2);
                wmma::mma_sync(acc2[0], a0, b1, acc2[0]);
                wmma::mma_sync(acc2[1], a1, b1, acc2[1]);
            }
            if (more) {
#pragma unroll
                for (int i = 0; i < 4; ++i)
                    *(int4*)(WB + ((cb + 1) & 1) * WBUF + pj[i] * WLD2 + pk[i]) = pst[i];
            }
            __syncthreads();
        }

        wmma::store_matrix_sync(&Sf[mrow0 * PQLD + np6 * 16], acc2[0], PQLD, wmma::mem_row_major);
        wmma::store_matrix_sync(&Sf[(mrow0 + 16) * PQLD + np6 * 16], acc2[1], PQLD, wmma::mem_row_major);
        __syncthreads();

        for (int t = tid; t < 49 * 96; t += NT) {
            int r = t / 96, cc = t % 96;
            out[((size_t)w * NTOK + r) * CDIM + p * 96 + cc] = Sf[r * PQLD + cc] + par[1152 + p * 96 + cc];
        }
        __syncthreads();
    }
}

// ---------------------------------------------------------------------------
extern "C" void kernel_launch(void* const* d_in, const int* in_sizes, int n_in,
                              void* d_out, int out_size)
{
    const float *x = 0, *mask = 0, *qkv_w = 0, *qkv_b = 0;
    const float *proj_w = 0, *proj_b = 0, *rpb = 0, *lamb = 0;

    for (int i = 0; i < n_in; ++i) {
        const float* p = (const float*)d_in[i];
        switch (in_sizes[i]) {
            case 77070336: x      = p; break;
            case 2458624:  mask   = p; break;
            case 442368:   qkv_w  = p; break;
            case 1152:     qkv_b  = p; break;
            case 147456:   proj_w = p; break;
            case 384:      proj_b = p; break;
            case 2028:     rpb    = p; break;
            case 12:       lamb   = p; break;
            default: break;
        }
    }
    if (!x || !mask || !qkv_w || !qkv_b || !proj_w || !proj_b || !rpb || !lamb) {
        x      = (const float*)d_in[0];
        mask   = (const float*)d_in[1];
        qkv_w  = (const float*)d_in[2];
        qkv_b  = (const float*)d_in[3];
        proj_w = (const float*)d_in[4];
        proj_b = (const float*)d_in[5];
        rpb    = (const float*)d_in[6];
        lamb   = (const float*)d_in[7];
    }

    prep_weights<<<(NQKV + NPJ + 255) / 256, 256>>>(qkv_w, proj_w);

    cudaFuncSetAttribute(winattn_kernel,
                         cudaFuncAttributeMaxDynamicSharedMemorySize, SMEM_BYTES);
    winattn_kernel<<<B_WIN, NT, SMEM_BYTES>>>(
        x, mask, qkv_b, proj_b, rpb, lamb, (float*)d_out);
}

// round 17
// speedup vs baseline: 1.0572x; 1.0572x over previous
#include <cuda_runtime.h>
#include <cuda_fp16.h>
#include <mma.h>
#include <cstdint>

using namespace nvcuda;

// Problem constants
#define B_WIN   4096
#define NTOK    49
#define CDIM    384
#define NHEADS  12
#define HDIM    32
#define NWIN    1024
#define SCALE_Q 0.17677669529663687f  // 32^-0.5

// Precomputed-weight globals (~1.2 MB)
__device__ __align__(256) __half g_wqkv[NHEADS * 96 * CDIM];  // head-permuted qkv_w
__device__ __align__(256) __half g_wpj[CDIM * CDIM];          // proj_w fp16

// Shared memory layout (byte offsets) — identical to R15 (2,453 µs)
#define SM_XH   0        // Xh: 64 x 392 half = 50176
#define SM_SF   50176    // GEMM staging 64x196 f32 | S 2x64x68 f32 + Sh 2x64x72 half
#define SM_WB   103424   // W staging 2 x 13824 halves = 55296 B; qkv aliases
#define SM_OH   158720   // Oh: 64 x 392 half = 50176
#define SM_MS   208896   // mask f32: 49 x 50 = 9800 (+pad)
#define SM_RB   218696   // rpb all heads fp16: 12 x 169 = 4056 (+pad)
#define SM_PAR  222752   // qkv_b(1152)+proj_b(384)+lamb(12) f32 = 6192
#define SMEM_BYTES 228944

#define XLD   392        // Xh/Oh ld (halves)
#define WLD   72         // qkv W staging ld (halves)
#define WBUF  13824      // halves per W buffer
#define KVLD  40         // qkv ld (halves)
#define QLD   196        // GEMM staging ld (floats)
#define SLD   68         // S f32 ld
#define SHLD  72         // Sh ld (halves)
#define PQLD  100        // proj staging ld (floats)
#define SH_OFF 34816     // byte offset of Sh inside SF region
#define WLD2  136        // proj W staging ld (halves), Kc=128 (+8 pad)
#define NT    384

// ---------------------------------------------------------------------------
// Fused weight precompute (single kernel so ncu -s 5 lands on the main kernel)
// ---------------------------------------------------------------------------
#define NQKV (NHEADS * 96 * CDIM)     // 442368
#define NPJ  (CDIM * CDIM)            // 147456
__global__ void prep_weights(const float* __restrict__ qkv_w,
                             const float* __restrict__ proj_w)
{
    int idx = blockIdx.x * 256 + threadIdx.x;
    if (idx < NQKV) {
        int h   = idx / (96 * CDIM);
        int rem = idx % (96 * CDIM);
        int j   = rem / CDIM;
        int k   = rem % CDIM;
        int g   = (j >> 5) * CDIM + h * HDIM + (j & 31);
        g_wqkv[idx] = __float2half_rn(qkv_w[(size_t)g * CDIM + k]);
    } else if (idx < NQKV + NPJ) {
        int i2 = idx - NQKV;
        g_wpj[i2] = __float2half_rn(proj_w[i2]);
    }
}

// ---------------------------------------------------------------------------
// Fused window attention: R15 structure + strength-reduced elementwise passes.
// ---------------------------------------------------------------------------
__global__ void __launch_bounds__(NT, 1)
winattn_kernel(const float* __restrict__ x,
               const float* __restrict__ mask,
               const float* __restrict__ qkv_b,
               const float* __restrict__ proj_b,
               const float* __restrict__ rpb,
               const float* __restrict__ lamb,
               float* __restrict__ out)
{
    extern __shared__ __align__(16) char smraw[];
    __half* Xh  = (__half*)(smraw + SM_XH);
    float*  Sf  = (float*)(smraw + SM_SF);
    __half* Sh  = (__half*)(smraw + SM_SF + SH_OFF);
    __half* WB  = (__half*)(smraw + SM_WB);
    __half* qkv = WB;                               // aliases WB (phase-disjoint)
    __half* Oh  = (__half*)(smraw + SM_OH);
    float*  ms  = (float*)(smraw + SM_MS);
    __half* rb  = (__half*)(smraw + SM_RB);
    float*  par = (float*)(smraw + SM_PAR);

    const int tid = threadIdx.x;
    const int wp  = tid >> 5;
    const int l   = tid & 31;
    const int w   = blockIdx.x;

    // qkv GEMM staging map: 192x64-half chunk = 1536 int4, 4 per thread
    int sj[4], sk[4];
#pragma unroll
    for (int i = 0; i < 4; ++i) {
        int v = tid + i * NT;
        sj[i] = v >> 3;
        sk[i] = (v & 7) << 3;
    }
    // proj staging map: 96x128-half chunk = 1536 int4, 4 per thread
    int pj[4], pk[4];
#pragma unroll
    for (int i = 0; i < 4; ++i) {
        int v = tid + i * NT;
        pj[i] = v >> 4;
        pk[i] = (v & 15) << 3;
    }

    // ---- per-thread fixed coordinates for elementwise passes ----
    // qkv convert pass: 49x192 grid; column fixed, rows strided by 2
    const int qc_cc = tid % 192;
    const int qc_r0 = tid / 192;                 // 0 or 1
    const int qc_hh = qc_cc / 96;
    const int qc_c2 = qc_cc % 96;
    const int qc_wh = qc_c2 >> 5;                // which (q|k|v)
    const int qc_d  = qc_c2 & 31;
    const float qc_scale = (qc_wh == 0) ? SCALE_Q : 1.0f;
    __half* const qc_dst = qkv + qc_hh * 7680 + qc_wh * 2560 + qc_d;
    // O convert pass: 49x64 grid; column fixed, rows strided by 6
    const int oc_cc = tid % 64;
    const int oc_r0 = tid / 64;                  // 0..5
    const int oc_hh = oc_cc >> 5;
    const int oc_d  = oc_cc & 31;
    // out store pass: 49x96 grid; column fixed, rows strided by 4
    const int os_cc = tid % 96;
    const int os_r0 = tid / 96;                  // 0..3
    // x load pass: 49 rows x 96 float4; column fixed, rows strided by 4
    const int xl_c4 = (tid % 96) * 4;
    const int xl_r0 = tid / 96;

    // ---- init ----
    for (int r = xl_r0; r < NTOK; r += 4) {
        float4 v = *(const float4*)&x[((size_t)w * NTOK + r) * CDIM + xl_c4];
        *(__half2*)&Xh[r * XLD + xl_c4]     = __floats2half2_rn(v.x, v.y);
        *(__half2*)&Xh[r * XLD + xl_c4 + 2] = __floats2half2_rn(v.z, v.w);
    }
    for (int t = tid; t < 15 * 196; t += NT) {        // zero pad rows 49..63
        int r = 49 + t / 196, c2 = (t % 196) * 2;
        __half2 z = __floats2half2_rn(0.0f, 0.0f);
        *(__half2*)&Xh[r * XLD + c2] = z;
        *(__half2*)&Oh[r * XLD + c2] = z;
    }
    {
        const float* mrow = mask + (size_t)(w & (NWIN - 1)) * (NTOK * NTOK);
        for (int t = tid; t < NTOK * NTOK; t += NT)
            ms[(t / 49) * 50 + (t % 49)] = mrow[t];
    }
    for (int t = tid; t < NHEADS * 169; t += NT)
        rb[t] = __float2half_rn(rpb[(t % 169) * NHEADS + (t / 169)]);
    for (int t = tid; t < 1548; t += NT)
        par[t] = (t < 1152) ? qkv_b[t] : (t < 1536 ? proj_b[t - 1152] : lamb[t - 1536]);
    __syncthreads();

    const int mrow0 = (wp & 1) * 32;     // GEMM m-base (2 x 16-row frags)
    const int ngq   = (wp >> 1) * 32;    // QKV GEMM n-base (6 groups of 32)

    // softmax lane constants: rpb index = base(i) + off, off per lane
    const int j0 = l, j1 = l + 32;
    const int off0 = 84 - 13 * (j0 / 7) - (j0 % 7);
    const int off1 = 84 - 13 * (j1 / 7) - (j1 % 7);

    // =============== 6 groups of 2 heads ===============
    for (int g = 0; g < 6; ++g) {
        const int h0 = 2 * g;
        const __half* Wg = g_wqkv + (size_t)h0 * (96 * CDIM);

        // ---- QKV GEMM: 64x192 = Xh @ Wg^T, Kc=64, register-staged dbl buffer ----
        wmma::fragment<wmma::accumulator, 16, 16, 16, float> acc[2][2];
#pragma unroll
        for (int i = 0; i < 2; ++i)
#pragma unroll
            for (int j = 0; j < 2; ++j) wmma::fill_fragment(acc[i][j], 0.0f);

        int4 st[4];
#pragma unroll
        for (int i = 0; i < 4; ++i)
            st[i] = *(const int4*)(Wg + (size_t)sj[i] * CDIM + sk[i]);
#pragma unroll
        for (int i = 0; i < 4; ++i)
            *(int4*)(WB + sj[i] * WLD + sk[i]) = st[i];
        __syncthreads();

        for (int c = 0; c < 6; ++c) {
            if (c < 5) {
#pragma unroll
                for (int i = 0; i < 4; ++i)
                    st[i] = *(const int4*)(Wg + (size_t)sj[i] * CDIM + (c + 1) * 64 + sk[i]);
            }
            const __half* Wc = WB + (c & 1) * WBUF;
#pragma unroll
            for (int ks = 0; ks < 4; ++ks) {
                wmma::fragment<wmma::matrix_a, 16, 16, 16, __half, wmma::row_major> a0, a1;
                wmma::load_matrix_sync(a0, &Xh[mrow0 * XLD + c * 64 + ks * 16], XLD);
                wmma::load_matrix_sync(a1, &Xh[(mrow0 + 16) * XLD + c * 64 + ks * 16], XLD);
                wmma::fragment<wmma::matrix_b, 16, 16, 16, __half, wmma::col_major> b0, b1;
                wmma::load_matrix_sync(b0, &Wc[ngq * WLD + ks * 16], WLD);
                wmma::load_matrix_sync(b1, &Wc[(ngq + 16) * WLD + ks * 16], WLD);
                wmma::mma_sync(acc[0][0], a0, b0, acc[0][0]);
                wmma::mma_sync(acc[0][1], a0, b1, acc[0][1]);
                wmma::mma_sync(acc[1][0], a1, b0, acc[1][0]);
                wmma::mma_sync(acc[1][1], a1, b1, acc[1][1]);
            }
            if (c < 5) {
#pragma unroll
                for (int i = 0; i < 4; ++i)
                    *(int4*)(WB + ((c + 1) & 1) * WBUF + sj[i] * WLD + sk[i]) = st[i];
            }
            __syncthreads();
        }
#pragma unroll
        for (int i = 0; i < 2; ++i)
#pragma unroll
            for (int j = 0; j < 2; ++j)
                wmma::store_matrix_sync(&Sf[(mrow0 + i * 16) * QLD + ngq + j * 16],
                                        acc[i][j], QLD, wmma::mem_row_major);
        __syncthreads();

        // ---- bias + q-scale + convert -> qkv fp16 (strength-reduced) ----
        {
            const float bias = par[qc_wh * CDIM + (h0 + qc_hh) * HDIM + qc_d];
            const float* srcF = Sf + qc_cc;
            for (int r = qc_r0; r < NTOK; r += 2)
                qc_dst[r * KVLD] = __float2half_rn((srcF[r * QLD] + bias) * qc_scale);
        }
        __syncthreads();

        // ---- S = q @ k^T : 32 tiles over 12 warps ----
        for (int t = wp; t < 32; t += 12) {
            int hh = t >> 4, mi = (t >> 2) & 3, nj = t & 3;
            const __half* qh = qkv + hh * 7680;
            const __half* kh = qh + 2560;
            wmma::fragment<wmma::accumulator, 16, 16, 16, float> sacc;
            wmma::fill_fragment(sacc, 0.0f);
#pragma unroll
            for (int ks = 0; ks < 2; ++ks) {
                wmma::fragment<wmma::matrix_a, 16, 16, 16, __half, wmma::row_major> a1;
                wmma::fragment<wmma::matrix_b, 16, 16, 16, __half, wmma::col_major> b1;
                wmma::load_matrix_sync(a1, &qh[mi * 16 * KVLD + ks * 16], KVLD);
                wmma::load_matrix_sync(b1, &kh[nj * 16 * KVLD + ks * 16], KVLD);
                wmma::mma_sync(sacc, a1, b1, sacc);
            }
            wmma::store_matrix_sync(&Sf[hh * 4352 + mi * 16 * SLD + nj * 16],
                                    sacc, SLD, wmma::mem_row_major);
        }
        __syncthreads();

        // ---- softmax (+rpb+mask, lamb rescale) -> Sh fp16; zero pads ----
        for (int i2 = wp; i2 < 128; i2 += 12) {
            int hh = i2 >> 6, i = i2 & 63;
            __half* ShH = Sh + hh * 4608;
            if (i < NTOK) {
                const float lam1 = 1.0f + par[1536 + h0 + hh];
                const float invn = 1.0f / (float)NTOK;
                const __half* rbh = rb + (h0 + hh) * 169;
                const int base_i = (i / 7) * 13 + (i % 7);
                float s0 = Sf[hh * 4352 + i * SLD + j0]
                         + __half2float(rbh[base_i + off0]) + ms[i * 50 + j0];
                float s1 = -1e30f;
                if (j1 < NTOK)
                    s1 = Sf[hh * 4352 + i * SLD + j1]
                       + __half2float(rbh[base_i + off1]) + ms[i * 50 + j1];
                float mx = fmaxf(s0, s1);
#pragma unroll
                for (int off = 16; off > 0; off >>= 1)
                    mx = fmaxf(mx, __shfl_xor_sync(0xffffffffu, mx, off));
                float e0 = __expf(s0 - mx);
                float e1 = (j1 < NTOK) ? __expf(s1 - mx) : 0.0f;
                float sm = e0 + e1;
#pragma unroll
                for (int off = 16; off > 0; off >>= 1)
                    sm += __shfl_xor_sync(0xffffffffu, sm, off);
                const float inv = 1.0f / sm;
                ShH[i * SHLD + j0] = __float2half_rn(invn + (e0 * inv - invn) * lam1);
                ShH[i * SHLD + j1] = (j1 < NTOK)
                    ? __float2half_rn(invn + (e1 * inv - invn) * lam1)
                    : __float2half_rn(0.0f);
            } else {
                ShH[i * SHLD + l]      = __float2half_rn(0.0f);
                ShH[i * SHLD + l + 32] = __float2half_rn(0.0f);
            }
        }
        __syncthreads();

        // ---- O = attn @ v : 16 tiles over 12 warps ----
        for (int t = wp; t < 16; t += 12) {
            int hh = t >> 3, mi = (t >> 1) & 3, nj = t & 1;
            const __half* ShH = Sh + hh * 4608;
            const __half* vhh = qkv + hh * 7680 + 5120;
            wmma::fragment<wmma::accumulator, 16, 16, 16, float> oacc;
            wmma::fill_fragment(oacc, 0.0f);
#pragma unroll
            for (int ks = 0; ks < 4; ++ks) {
                wmma::fragment<wmma::matrix_a, 16, 16, 16, __half, wmma::row_major> a1;
                wmma::fragment<wmma::matrix_b, 16, 16, 16, __half, wmma::row_major> b1;
                wmma::load_matrix_sync(a1, &ShH[mi * 16 * SHLD + ks * 16], SHLD);
                wmma::load_matrix_sync(b1, &vhh[ks * 16 * KVLD + nj * 16], KVLD);
                wmma::mma_sync(oacc, a1, b1, oacc);
            }
            wmma::store_matrix_sync(&Sf[hh * 4352 + mi * 16 * SLD + nj * 16],
                                    oacc, SLD, wmma::mem_row_major);
        }
        __syncthreads();

        // ---- convert O -> Oh (strength-reduced) ----
        {
            const float* srcF = Sf + oc_hh * 4352 + oc_d;
            __half* dstH = Oh + (h0 + oc_hh) * HDIM + oc_d;
            for (int r = oc_r0; r < NTOK; r += 6)
                dstH[r * XLD] = __float2half_rn(srcF[r * SLD]);
        }
        __syncthreads();
    }

    // =============== proj: out = Oh @ proj_w^T + b (single fp16, Kc=128) ===============
    const int np6 = (wp >> 1);      // n-tile 0..5 (16 cols each)

    int4 pst[4];
#pragma unroll
    for (int i = 0; i < 4; ++i)
        pst[i] = *(const int4*)(g_wpj + (size_t)pj[i] * CDIM + pk[i]);
#pragma unroll
    for (int i = 0; i < 4; ++i)
        *(int4*)(WB + pj[i] * WLD2 + pk[i]) = pst[i];
    __syncthreads();

    int cb = 0;   // global chunk parity: current chunk resides in buf (cb & 1)
    for (int p = 0; p < 4; ++p) {
        wmma::fragment<wmma::accumulator, 16, 16, 16, float> acc2[2];
        wmma::fill_fragment(acc2[0], 0.0f);
        wmma::fill_fragment(acc2[1], 0.0f);

        for (int c = 0; c < 3; ++c, ++cb) {
            const bool more = (c < 2) || (p < 3);
            if (more) {
                const int np_ = (c < 2) ? p : p + 1;
                const int nc_ = (c < 2) ? c + 1 : 0;
#pragma unroll
                for (int i = 0; i < 4; ++i)
                    pst[i] = *(const int4*)(g_wpj
                             + (size_t)(np_ * 96 + pj[i]) * CDIM + nc_ * 128 + pk[i]);
            }
            const __half* Wc = WB + (cb & 1) * WBUF;
#pragma unroll
            for (int ks = 0; ks < 8; ++ks) {
                wmma::fragment<wmma::matrix_a, 16, 16, 16, __half, wmma::row_major> a0, a1;
                wmma::load_matrix_sync(a0, &Oh[mrow0 * XLD + c * 128 + ks * 16], XLD);
                wmma::load_matrix_sync(a1, &Oh[(mrow0 + 16) * XLD + c * 128 + ks * 16], XLD);
                wmma::fragment<wmma::matrix_b, 16, 16, 16, __half, wmma::col_major> b1;
                wmma::load_matrix_sync(b1, &Wc[np6 * 16 * WLD2 + ks * 16], WLD2);
                wmma::mma_sync(acc2[0], a0, b1, acc2[0]);
                wmma::mma_sync(acc2[1], a1, b1, acc2[1]);
            }
            if (more) {
#pragma unroll
                for (int i = 0; i < 4; ++i)
                    *(int4*)(WB + ((cb + 1) & 1) * WBUF + pj[i] * WLD2 + pk[i]) = pst[i];
            }
            __syncthreads();
        }

        wmma::store_matrix_sync(&Sf[mrow0 * PQLD + np6 * 16], acc2[0], PQLD, wmma::mem_row_major);
        wmma::store_matrix_sync(&Sf[(mrow0 + 16) * PQLD + np6 * 16], acc2[1], PQLD, wmma::mem_row_major);
        __syncthreads();

        // ---- out store (strength-reduced) ----
        {
            const float bias = par[1152 + p * 96 + os_cc];
            const float* srcF = Sf + os_cc;
            float* dstG = out + (size_t)w * NTOK * CDIM + p * 96 + os_cc;
            for (int r = os_r0; r < NTOK; r += 4)
                dstG[(size_t)r * CDIM] = srcF[r * PQLD] + bias;
        }
        __syncthreads();
    }
}

// ---------------------------------------------------------------------------
extern "C" void kernel_launch(void* const* d_in, const int* in_sizes, int n_in,
                              void* d_out, int out_size)
{
    const float *x = 0, *mask = 0, *qkv_w = 0, *qkv_b = 0;
    const float *proj_w = 0, *proj_b = 0, *rpb = 0, *lamb = 0;

    for (int i = 0; i < n_in; ++i) {
        const float* p = (const float*)d_in[i];
        switch (in_sizes[i]) {
            case 77070336: x      = p; break;
            case 2458624:  mask   = p; break;
            case 442368:   qkv_w  = p; break;
            case 1152:     qkv_b  = p; break;
            case 147456:   proj_w = p; break;
            case 384:      proj_b = p; break;
            case 2028:     rpb    = p; break;
            case 12:       lamb   = p; break;
            default: break;
        }
    }
    if (!x || !mask || !qkv_w || !qkv_b || !proj_w || !proj_b || !rpb || !lamb) {
        x      = (const float*)d_in[0];
        mask   = (const float*)d_in[1];
        qkv_w  = (const float*)d_in[2];
        qkv_b  = (const float*)d_in[3];
        proj_w = (const float*)d_in[4];
        proj_b = (const float*)d_in[5];
        rpb    = (const float*)d_in[6];
        lamb   = (const float*)d_in[7];
    }

    prep_weights<<<(NQKV + NPJ + 255) / 256, 256>>>(qkv_w, proj_w);

    cudaFuncSetAttribute(winattn_kernel,
                         cudaFuncAttributeMaxDynamicSharedMemorySize, SMEM_BYTES);
    winattn_kernel<<<B_WIN, NT, SMEM_BYTES>>>(
        x, mask, qkv_b, proj_b, rpb, lamb, (float*)d_out);
}